// round 5
// baseline (speedup 1.0000x reference)
#include <cuda_runtime.h>
#include <stdint.h>
#include <math.h>
#include <mma.h>

using namespace nvcuda;

#define M_TOK   4096     // B*L
#define D_MODEL 256
#define HDIM    512      // H*DH
#define L_SEQ   512
#define NHEAD   8
#define DHEAD   64
#define DEPTH_N 16
#define INNER_N 1024

// ---------------- scratch (device globals; no allocation allowed) -------------
__device__ float g_x   [M_TOK * D_MODEL];
__device__ float g_h   [M_TOK * D_MODEL];
__device__ float g_t   [M_TOK * D_MODEL];
__device__ float g_q   [M_TOK * HDIM];
__device__ float g_k   [M_TOK * HDIM];
__device__ float g_v   [M_TOK * HDIM];
__device__ float g_attn[M_TOK * HDIM];
__device__ float g_u   [M_TOK * 2 * INNER_N];
__device__ float g_ua  [M_TOK * INNER_N];

// ---------------- cp.async helpers -------------------------------------------
__device__ __forceinline__ void cp16(uint32_t dst, const float* src) {
    asm volatile("cp.async.ca.shared.global [%0], [%1], 16;\n" :: "r"(dst), "l"(src));
}
__device__ __forceinline__ void cp_commit() {
    asm volatile("cp.async.commit_group;\n");
}
__device__ __forceinline__ void cp_wait1() {
    asm volatile("cp.async.wait_group 1;\n");
}
__device__ __forceinline__ void cp_wait0() {
    asm volatile("cp.async.wait_group 0;\n");
}

// ---------------- LayerNorm helper (blockDim.x == 256 == D_MODEL) ------------
__device__ __forceinline__ void ln_write(float v, const float* __restrict__ g,
                                         const float* __restrict__ b,
                                         float* __restrict__ y, int row) {
    int d = threadIdx.x;
    float s = v, s2 = v * v;
    #pragma unroll
    for (int o = 16; o > 0; o >>= 1) {
        s  += __shfl_down_sync(0xffffffffu, s,  o);
        s2 += __shfl_down_sync(0xffffffffu, s2, o);
    }
    __shared__ float ws[8], ws2[8];
    __shared__ float mean_s, inv_s;
    int w = threadIdx.x >> 5, lane = threadIdx.x & 31;
    if (lane == 0) { ws[w] = s; ws2[w] = s2; }
    __syncthreads();
    if (threadIdx.x == 0) {
        float t = 0.f, t2 = 0.f;
        #pragma unroll
        for (int i = 0; i < 8; i++) { t += ws[i]; t2 += ws2[i]; }
        float mu  = t  * (1.f / 256.f);
        float var = t2 * (1.f / 256.f) - mu * mu;
        mean_s = mu;
        inv_s  = rsqrtf(var + 1e-5f);
    }
    __syncthreads();
    y[(size_t)row * D_MODEL + d] = (v - mean_s) * inv_s * g[d] + b[d];
}

__global__ void embed_ln_kernel(const int* __restrict__ seq,
                                const float* __restrict__ emb,
                                const float* __restrict__ g,
                                const float* __restrict__ b,
                                float* __restrict__ y) {
    int row = blockIdx.x;
    float v = emb[(size_t)seq[row] * D_MODEL + threadIdx.x];
    ln_write(v, g, b, y, row);
}

__global__ void ln_kernel(const float* __restrict__ x,
                          const float* __restrict__ g,
                          const float* __restrict__ b,
                          float* __restrict__ y) {
    int row = blockIdx.x;
    float v = x[(size_t)row * D_MODEL + threadIdx.x];
    ln_write(v, g, b, y, row);
}

// x[row] += t[row] (+bias); then y[row] = LN(x[row])
__global__ void add_ln_kernel(float* __restrict__ x,
                              const float* __restrict__ t,
                              const float* __restrict__ bias,
                              const float* __restrict__ g,
                              const float* __restrict__ b,
                              float* __restrict__ y) {
    int row = blockIdx.x;
    int d = threadIdx.x;
    size_t idx = (size_t)row * D_MODEL + d;
    float v = x[idx] + t[idx];
    if (bias) v += bias[d];
    x[idx] = v;
    ln_write(v, g, b, y, row);
}

// ---------------- tf32 WMMA GEMM body: 128x64 tile, BK=32, double-buffered ---
// smem layout: As[2][128][36], Bs[2][32][68] (dynamic, 54272 bytes)
#define AS_STAGE (128 * 36)
#define BS_STAGE (32 * 68)
#define GEMM_SMEM ((2 * AS_STAGE + 2 * BS_STAGE) * 4)

__device__ __forceinline__ void gemm_body(const float* __restrict__ A,
                                          const float* __restrict__ W,
                                          float* __restrict__ C,
                                          int N, int K, int bm, int bn) {
    extern __shared__ float dyn[];
    float* As = dyn;
    float* Bs = dyn + 2 * AS_STAGE;
    const int tid = threadIdx.x;
    const int warp = tid >> 5, wm = warp & 3, wn = warp >> 2;
    const int arow = tid >> 1, acol = (tid & 1) * 16;
    const int brow = tid >> 3, bcol = (tid & 7) * 8;
    uint32_t as_u = (uint32_t)__cvta_generic_to_shared(As);
    uint32_t bs_u = (uint32_t)__cvta_generic_to_shared(Bs);

    wmma::fragment<wmma::accumulator, 16, 16, 8, float> acc[2][2];
    #pragma unroll
    for (int i = 0; i < 2; i++)
        #pragma unroll
        for (int j = 0; j < 2; j++)
            wmma::fill_fragment(acc[i][j], 0.0f);

    const int nk = K >> 5;

    // prologue: stage 0
    {
        const float* ap = A + (size_t)(bm + arow) * K + acol;
        uint32_t ad = as_u + (uint32_t)((arow * 36 + acol) * 4);
        #pragma unroll
        for (int i = 0; i < 4; i++) cp16(ad + i * 16, ap + i * 4);
        const float* bp = W + (size_t)brow * N + bn + bcol;
        uint32_t bd = bs_u + (uint32_t)((brow * 68 + bcol) * 4);
        cp16(bd, bp); cp16(bd + 16, bp + 4);
        cp_commit();
    }

    for (int kt = 0; kt < nk; kt++) {
        int st = kt & 1;
        if (kt + 1 < nk) {
            int k0 = (kt + 1) << 5;
            int s2 = st ^ 1;
            const float* ap = A + (size_t)(bm + arow) * K + k0 + acol;
            uint32_t ad = as_u + (uint32_t)((s2 * AS_STAGE + arow * 36 + acol) * 4);
            #pragma unroll
            for (int i = 0; i < 4; i++) cp16(ad + i * 16, ap + i * 4);
            const float* bp = W + (size_t)(k0 + brow) * N + bn + bcol;
            uint32_t bd = bs_u + (uint32_t)((s2 * BS_STAGE + brow * 68 + bcol) * 4);
            cp16(bd, bp); cp16(bd + 16, bp + 4);
            cp_commit();
            cp_wait1();
        } else {
            cp_wait0();
        }
        __syncthreads();

        const float* Ab = As + st * AS_STAGE;
        const float* Bb = Bs + st * BS_STAGE;
        #pragma unroll
        for (int kk = 0; kk < 4; kk++) {
            wmma::fragment<wmma::matrix_a, 16, 16, 8, wmma::precision::tf32, wmma::row_major> af[2];
            wmma::fragment<wmma::matrix_b, 16, 16, 8, wmma::precision::tf32, wmma::row_major> bf[2];
            #pragma unroll
            for (int i = 0; i < 2; i++)
                wmma::load_matrix_sync(af[i], Ab + (wm * 32 + i * 16) * 36 + kk * 8, 36);
            #pragma unroll
            for (int j = 0; j < 2; j++)
                wmma::load_matrix_sync(bf[j], Bb + (kk * 8) * 68 + wn * 32 + j * 16, 68);
            #pragma unroll
            for (int i = 0; i < 2; i++)
                #pragma unroll
                for (int j = 0; j < 2; j++)
                    wmma::mma_sync(acc[i][j], af[i], bf[j], acc[i][j]);
        }
        __syncthreads();
    }

    #pragma unroll
    for (int i = 0; i < 2; i++)
        #pragma unroll
        for (int j = 0; j < 2; j++)
            wmma::store_matrix_sync(C + (size_t)(bm + wm * 32 + i * 16) * N + bn + wn * 32 + j * 16,
                                    acc[i][j], N, wmma::mem_row_major);
}

__global__ __launch_bounds__(256) void gemm_tf32(const float* __restrict__ A,
                                                 const float* __restrict__ W,
                                                 float* __restrict__ C, int N, int K) {
    gemm_body(A, W, C, N, K, blockIdx.y << 7, blockIdx.x << 6);
}

// fused QKV: blockIdx.x in [0,24); sel = x>>3 chooses weight/output
__global__ __launch_bounds__(256) void gemm_qkv(const float* __restrict__ A,
                                                const float* __restrict__ wq,
                                                const float* __restrict__ wk,
                                                const float* __restrict__ wv,
                                                float* __restrict__ qb,
                                                float* __restrict__ kb,
                                                float* __restrict__ vb) {
    int sel = blockIdx.x >> 3;
    const float* W = (sel == 0) ? wq : (sel == 1) ? wk : wv;
    float* C = (sel == 0) ? qb : (sel == 1) ? kb : vb;
    gemm_body(A, W, C, HDIM, D_MODEL, blockIdx.y << 7, (blockIdx.x & 7) << 6);
}

// ---------------- attention: 512 threads, WMMA QK^T + softmax + WMMA PV ------
#define SP 516   // score row stride

__global__ __launch_bounds__(512) void attn_kernel(const float* __restrict__ q,
                                                   const float* __restrict__ k,
                                                   const float* __restrict__ v,
                                                   const int* __restrict__ mask,
                                                   float* __restrict__ o) {
    extern __shared__ float sm[];
    float* Qs = sm;                     // [64][72]
    float* Ks = sm + 64 * 72;           // [64][72] (reused for V)
    float* S  = sm + 2 * 64 * 72;       // [64][SP]
    float* red    = S + 64 * SP;        // [512]
    float* rowsum = red + 512;          // [64]
    float* rowmax = rowsum + 64;        // [64]

    const int tid = threadIdx.x;
    const int warp = tid >> 5;
    const int wm = warp & 3;            // 16-row tile
    const int wn = warp >> 2;           // 16-col tile (of 64)
    const int qt = blockIdx.x;
    const int b  = blockIdx.y >> 3;
    const int h  = blockIdx.y & 7;
    const float slope = exp2f(-(float)(h + 1));
    const float scale = 0.125f;

    // load Q tile [64][64] row-major ld 72 (512 threads: 8 elems each)
    {
        int r = tid >> 3, c = (tid & 7) * 8;
        const float* qp = q + (size_t)(b * L_SEQ + qt * 64 + r) * HDIM + h * DHEAD + c;
        *(float4*)&Qs[r * 72 + c]     = *(const float4*)qp;
        *(float4*)&Qs[r * 72 + c + 4] = *(const float4*)(qp + 4);
    }

    // pass 1: raw S = Q K^T
    for (int kt = 0; kt < 8; kt++) {
        __syncthreads();
        {
            int r = tid >> 3, c = (tid & 7) * 8;
            const float* kp = k + (size_t)(b * L_SEQ + kt * 64 + r) * HDIM + h * DHEAD + c;
            *(float4*)&Ks[r * 72 + c]     = *(const float4*)kp;
            *(float4*)&Ks[r * 72 + c + 4] = *(const float4*)(kp + 4);
        }
        __syncthreads();
        wmma::fragment<wmma::accumulator, 16, 16, 8, float> sacc;
        wmma::fill_fragment(sacc, 0.0f);
        #pragma unroll
        for (int kk = 0; kk < 8; kk++) {
            wmma::fragment<wmma::matrix_a, 16, 16, 8, wmma::precision::tf32, wmma::row_major> af;
            wmma::fragment<wmma::matrix_b, 16, 16, 8, wmma::precision::tf32, wmma::col_major> bf;
            wmma::load_matrix_sync(af, &Qs[(wm * 16) * 72 + kk * 8], 72);
            wmma::load_matrix_sync(bf, &Ks[(wn * 16) * 72 + kk * 8], 72);
            wmma::mma_sync(sacc, af, bf, sacc);
        }
        wmma::store_matrix_sync(&S[(wm * 16) * SP + kt * 64 + wn * 16], sacc, SP,
                                wmma::mem_row_major);
    }
    __syncthreads();

    // pass 2: scale + alibi + mask, softmax, normalize in place
    {
        int r = tid >> 3, p = tid & 7;
        int ig = qt * 64 + r;
        float* Srow = S + r * SP;
        int base = p * 64;
        float mx = -3e38f;
        for (int jj = 0; jj < 64; jj++) {
            int j = base + jj;
            float s;
            if (mask[b * L_SEQ + j] != 0)
                s = Srow[j] * scale - slope * fabsf((float)(ig - j));
            else
                s = -1e9f;
            Srow[j] = s;
            mx = fmaxf(mx, s);
        }
        red[r * 8 + p] = mx;
        __syncthreads();
        if (p == 0) {
            float m2 = red[r * 8];
            #pragma unroll
            for (int i = 1; i < 8; i++) m2 = fmaxf(m2, red[r * 8 + i]);
            rowmax[r] = m2;
        }
        __syncthreads();
        float rm = rowmax[r];
        float sum = 0.f;
        for (int jj = 0; jj < 64; jj++) {
            float e = __expf(Srow[base + jj] - rm);
            Srow[base + jj] = e;
            sum += e;
        }
        __syncthreads();
        red[r * 8 + p] = sum;
        __syncthreads();
        if (p == 0) {
            float t2 = 0.f;
            #pragma unroll
            for (int i = 0; i < 8; i++) t2 += red[r * 8 + i];
            rowsum[r] = t2;
        }
        __syncthreads();
        float inv = 1.f / rowsum[r];
        for (int jj = 0; jj < 64; jj++)
            Srow[base + jj] *= inv;
    }

    // pass 3: O = P @ V
    wmma::fragment<wmma::accumulator, 16, 16, 8, float> oacc;
    wmma::fill_fragment(oacc, 0.0f);
    for (int vt = 0; vt < 8; vt++) {
        __syncthreads();
        {
            int r = tid >> 3, c = (tid & 7) * 8;
            const float* vp = v + (size_t)(b * L_SEQ + vt * 64 + r) * HDIM + h * DHEAD + c;
            *(float4*)&Ks[r * 72 + c]     = *(const float4*)vp;
            *(float4*)&Ks[r * 72 + c + 4] = *(const float4*)(vp + 4);
        }
        __syncthreads();
        #pragma unroll
        for (int kk = 0; kk < 8; kk++) {
            wmma::fragment<wmma::matrix_a, 16, 16, 8, wmma::precision::tf32, wmma::row_major> af;
            wmma::fragment<wmma::matrix_b, 16, 16, 8, wmma::precision::tf32, wmma::row_major> bf;
            wmma::load_matrix_sync(af, &S[(wm * 16) * SP + vt * 64 + kk * 8], SP);
            wmma::load_matrix_sync(bf, &Ks[(kk * 8) * 72 + wn * 16], 72);
            wmma::mma_sync(oacc, af, bf, oacc);
        }
    }
    wmma::store_matrix_sync(o + (size_t)(b * L_SEQ + qt * 64 + wm * 16) * HDIM
                              + h * DHEAD + wn * 16,
                            oacc, HDIM, wmma::mem_row_major);
}

// ---------------- GEGLU with fused b1 bias -----------------------------------
__global__ void glu_kernel(const float* __restrict__ u,
                           const float* __restrict__ b1,
                           float* __restrict__ ua) {
    int idx = blockIdx.x * blockDim.x + threadIdx.x;
    int m = idx >> 10, i = idx & 1023;
    float val  = u[(size_t)m * 2048 + i] + b1[i];
    float gate = u[(size_t)m * 2048 + 1024 + i] + b1[1024 + i];
    ua[idx] = val * gate * normcdff(gate);
}

// ---------------- final projection to 2 logits -------------------------------
__global__ void out_kernel(const float* __restrict__ hh,
                           const float* __restrict__ Wout,
                           const float* __restrict__ bout,
                           float* __restrict__ out) {
    int row = blockIdx.x;
    int d = threadIdx.x;
    float v = hh[(size_t)row * D_MODEL + d];
    float s0 = v * Wout[d * 2 + 0];
    float s1 = v * Wout[d * 2 + 1];
    #pragma unroll
    for (int o2 = 16; o2 > 0; o2 >>= 1) {
        s0 += __shfl_down_sync(0xffffffffu, s0, o2);
        s1 += __shfl_down_sync(0xffffffffu, s1, o2);
    }
    __shared__ float w0[8], w1[8];
    int w = threadIdx.x >> 5, lane = threadIdx.x & 31;
    if (lane == 0) { w0[w] = s0; w1[w] = s1; }
    __syncthreads();
    if (threadIdx.x == 0) {
        float t0 = 0.f, t1 = 0.f;
        #pragma unroll
        for (int i = 0; i < 8; i++) { t0 += w0[i]; t1 += w1[i]; }
        out[row * 2 + 0] = t0 + bout[0];
        out[row * 2 + 1] = t1 + bout[1];
    }
}

// ---------------- host orchestration -----------------------------------------
extern "C" void kernel_launch(void* const* d_in, const int* in_sizes, int n_in,
                              void* d_out, int out_size) {
    (void)in_sizes; (void)n_in; (void)out_size;
    const int*   seq  = (const int*)d_in[0];
    const int*   mask = (const int*)d_in[1];
    const float* emb  = (const float*)d_in[2];
    const float* png  = (const float*)d_in[3];
    const float* pnb  = (const float*)d_in[4];
    const float* ln1g = (const float*)d_in[5];
    const float* ln1b = (const float*)d_in[6];
    const float* Wq   = (const float*)d_in[7];
    const float* Wk   = (const float*)d_in[8];
    const float* Wv   = (const float*)d_in[9];
    const float* Wo   = (const float*)d_in[10];
    const float* ln2g = (const float*)d_in[11];
    const float* ln2b = (const float*)d_in[12];
    const float* W1   = (const float*)d_in[13];
    const float* b1   = (const float*)d_in[14];
    const float* W2   = (const float*)d_in[15];
    const float* b2   = (const float*)d_in[16];
    const float* fng  = (const float*)d_in[17];
    const float* fnb  = (const float*)d_in[18];
    const float* Wout = (const float*)d_in[19];
    const float* bout = (const float*)d_in[20];

    float *x, *h, *t, *qb, *kb, *vb, *ab, *ub, *uab;
    cudaGetSymbolAddress((void**)&x,   g_x);
    cudaGetSymbolAddress((void**)&h,   g_h);
    cudaGetSymbolAddress((void**)&t,   g_t);
    cudaGetSymbolAddress((void**)&qb,  g_q);
    cudaGetSymbolAddress((void**)&kb,  g_k);
    cudaGetSymbolAddress((void**)&vb,  g_v);
    cudaGetSymbolAddress((void**)&ab,  g_attn);
    cudaGetSymbolAddress((void**)&ub,  g_u);
    cudaGetSymbolAddress((void**)&uab, g_ua);

    const int attn_smem = (2 * 64 * 72 + 64 * SP + 512 + 64 + 64) * (int)sizeof(float);
    cudaFuncSetAttribute(attn_kernel, cudaFuncAttributeMaxDynamicSharedMemorySize, attn_smem);
    cudaFuncSetAttribute(gemm_tf32, cudaFuncAttributeMaxDynamicSharedMemorySize, GEMM_SMEM);
    cudaFuncSetAttribute(gemm_qkv,  cudaFuncAttributeMaxDynamicSharedMemorySize, GEMM_SMEM);

    embed_ln_kernel<<<M_TOK, 256>>>(seq, emb, png, pnb, x);
    ln_kernel<<<M_TOK, 256>>>(x, ln1g, ln1b, h);

    for (int l = 0; l < DEPTH_N; l++) {
        const float* wq  = Wq  + (size_t)l * D_MODEL * HDIM;
        const float* wk  = Wk  + (size_t)l * D_MODEL * HDIM;
        const float* wv  = Wv  + (size_t)l * D_MODEL * HDIM;
        const float* wo  = Wo  + (size_t)l * HDIM * D_MODEL;
        const float* w1  = W1  + (size_t)l * D_MODEL * 2 * INNER_N;
        const float* bb1 = b1  + (size_t)l * 2 * INNER_N;
        const float* w2  = W2  + (size_t)l * INNER_N * D_MODEL;
        const float* bb2 = b2  + (size_t)l * D_MODEL;

        gemm_qkv<<<dim3(24, 32), 256, GEMM_SMEM>>>(h, wq, wk, wv, qb, kb, vb);

        attn_kernel<<<dim3(L_SEQ / 64, 8 * NHEAD), 512, attn_smem>>>(qb, kb, vb, mask, ab);

        gemm_tf32<<<dim3(D_MODEL / 64, 32), 256, GEMM_SMEM>>>(ab, wo, t, D_MODEL, HDIM);
        add_ln_kernel<<<M_TOK, 256>>>(x, t, nullptr, ln2g + l * D_MODEL, ln2b + l * D_MODEL, h);

        gemm_tf32<<<dim3(2 * INNER_N / 64, 32), 256, GEMM_SMEM>>>(h, w1, ub, 2 * INNER_N, D_MODEL);
        glu_kernel<<<(M_TOK * INNER_N) / 256, 256>>>(ub, bb1, uab);

        gemm_tf32<<<dim3(D_MODEL / 64, 32), 256, GEMM_SMEM>>>(uab, w2, t, D_MODEL, INNER_N);
        if (l < DEPTH_N - 1)
            add_ln_kernel<<<M_TOK, 256>>>(x, t, bb2, ln1g + (l + 1) * D_MODEL,
                                          ln1b + (l + 1) * D_MODEL, h);
        else
            add_ln_kernel<<<M_TOK, 256>>>(x, t, bb2, fng, fnb, h);
    }

    out_kernel<<<M_TOK, 256>>>(h, Wout, bout, (float*)d_out);
}

// round 6
// speedup vs baseline: 1.0948x; 1.0948x over previous
#include <cuda_runtime.h>
#include <stdint.h>
#include <math.h>
#include <mma.h>

using namespace nvcuda;

#define M_TOK   4096     // B*L
#define D_MODEL 256
#define HDIM    512      // H*DH
#define L_SEQ   512
#define NHEAD   8
#define DHEAD   64
#define DEPTH_N 16
#define INNER_N 1024

// ---------------- scratch (device globals; no allocation allowed) -------------
__device__ float g_x   [M_TOK * D_MODEL];
__device__ float g_h   [M_TOK * D_MODEL];
__device__ float g_t   [M_TOK * D_MODEL];
__device__ float g_q   [M_TOK * HDIM];
__device__ float g_k   [M_TOK * HDIM];
__device__ float g_v   [M_TOK * HDIM];
__device__ float g_attn[M_TOK * HDIM];
__device__ float g_u   [M_TOK * 2 * INNER_N];
__device__ float g_ua  [M_TOK * INNER_N];

// ---------------- cp.async helpers -------------------------------------------
__device__ __forceinline__ void cp16(uint32_t dst, const float* src) {
    asm volatile("cp.async.ca.shared.global [%0], [%1], 16;\n" :: "r"(dst), "l"(src));
}
__device__ __forceinline__ void cp_commit() {
    asm volatile("cp.async.commit_group;\n");
}
__device__ __forceinline__ void cp_wait1() {
    asm volatile("cp.async.wait_group 1;\n");
}
__device__ __forceinline__ void cp_wait0() {
    asm volatile("cp.async.wait_group 0;\n");
}

// ---------------- LayerNorm helper (blockDim.x == 256 == D_MODEL) ------------
__device__ __forceinline__ void ln_write(float v, const float* __restrict__ g,
                                         const float* __restrict__ b,
                                         float* __restrict__ y, int row) {
    int d = threadIdx.x;
    float s = v, s2 = v * v;
    #pragma unroll
    for (int o = 16; o > 0; o >>= 1) {
        s  += __shfl_down_sync(0xffffffffu, s,  o);
        s2 += __shfl_down_sync(0xffffffffu, s2, o);
    }
    __shared__ float ws[8], ws2[8];
    __shared__ float mean_s, inv_s;
    int w = threadIdx.x >> 5, lane = threadIdx.x & 31;
    if (lane == 0) { ws[w] = s; ws2[w] = s2; }
    __syncthreads();
    if (threadIdx.x == 0) {
        float t = 0.f, t2 = 0.f;
        #pragma unroll
        for (int i = 0; i < 8; i++) { t += ws[i]; t2 += ws2[i]; }
        float mu  = t  * (1.f / 256.f);
        float var = t2 * (1.f / 256.f) - mu * mu;
        mean_s = mu;
        inv_s  = rsqrtf(var + 1e-5f);
    }
    __syncthreads();
    y[(size_t)row * D_MODEL + d] = (v - mean_s) * inv_s * g[d] + b[d];
}

__global__ void embed_ln_kernel(const int* __restrict__ seq,
                                const float* __restrict__ emb,
                                const float* __restrict__ g,
                                const float* __restrict__ b,
                                float* __restrict__ y) {
    int row = blockIdx.x;
    float v = emb[(size_t)seq[row] * D_MODEL + threadIdx.x];
    ln_write(v, g, b, y, row);
}

__global__ void ln_kernel(const float* __restrict__ x,
                          const float* __restrict__ g,
                          const float* __restrict__ b,
                          float* __restrict__ y) {
    int row = blockIdx.x;
    float v = x[(size_t)row * D_MODEL + threadIdx.x];
    ln_write(v, g, b, y, row);
}

// x[row] += t[row] (+bias); then y[row] = LN(x[row])
__global__ void add_ln_kernel(float* __restrict__ x,
                              const float* __restrict__ t,
                              const float* __restrict__ bias,
                              const float* __restrict__ g,
                              const float* __restrict__ b,
                              float* __restrict__ y) {
    int row = blockIdx.x;
    int d = threadIdx.x;
    size_t idx = (size_t)row * D_MODEL + d;
    float v = x[idx] + t[idx];
    if (bias) v += bias[d];
    x[idx] = v;
    ln_write(v, g, b, y, row);
}

// ---------------- tf32 WMMA GEMM body: 128x64 tile, BK=32, double-buffered ---
#define AS_STAGE (128 * 36)
#define BS_STAGE (32 * 68)
#define GEMM_SMEM ((2 * AS_STAGE + 2 * BS_STAGE) * 4)

__device__ __forceinline__ void gemm_body(const float* __restrict__ A,
                                          const float* __restrict__ W,
                                          float* __restrict__ C,
                                          int N, int K, int bm, int bn) {
    extern __shared__ float dyn[];
    float* As = dyn;
    float* Bs = dyn + 2 * AS_STAGE;
    const int tid = threadIdx.x;
    const int warp = tid >> 5, wm = warp & 3, wn = warp >> 2;
    const int arow = tid >> 1, acol = (tid & 1) * 16;
    const int brow = tid >> 3, bcol = (tid & 7) * 8;
    uint32_t as_u = (uint32_t)__cvta_generic_to_shared(As);
    uint32_t bs_u = (uint32_t)__cvta_generic_to_shared(Bs);

    wmma::fragment<wmma::accumulator, 16, 16, 8, float> acc[2][2];
    #pragma unroll
    for (int i = 0; i < 2; i++)
        #pragma unroll
        for (int j = 0; j < 2; j++)
            wmma::fill_fragment(acc[i][j], 0.0f);

    const int nk = K >> 5;

    // prologue: stage 0
    {
        const float* ap = A + (size_t)(bm + arow) * K + acol;
        uint32_t ad = as_u + (uint32_t)((arow * 36 + acol) * 4);
        #pragma unroll
        for (int i = 0; i < 4; i++) cp16(ad + i * 16, ap + i * 4);
        const float* bp = W + (size_t)brow * N + bn + bcol;
        uint32_t bd = bs_u + (uint32_t)((brow * 68 + bcol) * 4);
        cp16(bd, bp); cp16(bd + 16, bp + 4);
        cp_commit();
    }

    for (int kt = 0; kt < nk; kt++) {
        int st = kt & 1;
        if (kt + 1 < nk) {
            int k0 = (kt + 1) << 5;
            int s2 = st ^ 1;
            const float* ap = A + (size_t)(bm + arow) * K + k0 + acol;
            uint32_t ad = as_u + (uint32_t)((s2 * AS_STAGE + arow * 36 + acol) * 4);
            #pragma unroll
            for (int i = 0; i < 4; i++) cp16(ad + i * 16, ap + i * 4);
            const float* bp = W + (size_t)(k0 + brow) * N + bn + bcol;
            uint32_t bd = bs_u + (uint32_t)((s2 * BS_STAGE + brow * 68 + bcol) * 4);
            cp16(bd, bp); cp16(bd + 16, bp + 4);
            cp_commit();
            cp_wait1();
        } else {
            cp_wait0();
        }
        __syncthreads();

        const float* Ab = As + st * AS_STAGE;
        const float* Bb = Bs + st * BS_STAGE;
        #pragma unroll
        for (int kk = 0; kk < 4; kk++) {
            wmma::fragment<wmma::matrix_a, 16, 16, 8, wmma::precision::tf32, wmma::row_major> af[2];
            wmma::fragment<wmma::matrix_b, 16, 16, 8, wmma::precision::tf32, wmma::row_major> bf[2];
            #pragma unroll
            for (int i = 0; i < 2; i++) {
                wmma::load_matrix_sync(af[i], Ab + (wm * 32 + i * 16) * 36 + kk * 8, 36);
                #pragma unroll
                for (int e = 0; e < af[i].num_elements; e++)
                    af[i].x[e] = wmma::__float_to_tf32(af[i].x[e]);
            }
            #pragma unroll
            for (int j = 0; j < 2; j++) {
                wmma::load_matrix_sync(bf[j], Bb + (kk * 8) * 68 + wn * 32 + j * 16, 68);
                #pragma unroll
                for (int e = 0; e < bf[j].num_elements; e++)
                    bf[j].x[e] = wmma::__float_to_tf32(bf[j].x[e]);
            }
            #pragma unroll
            for (int i = 0; i < 2; i++)
                #pragma unroll
                for (int j = 0; j < 2; j++)
                    wmma::mma_sync(acc[i][j], af[i], bf[j], acc[i][j]);
        }
        __syncthreads();
    }

    #pragma unroll
    for (int i = 0; i < 2; i++)
        #pragma unroll
        for (int j = 0; j < 2; j++)
            wmma::store_matrix_sync(C + (size_t)(bm + wm * 32 + i * 16) * N + bn + wn * 32 + j * 16,
                                    acc[i][j], N, wmma::mem_row_major);
}

__global__ __launch_bounds__(256) void gemm_tf32(const float* __restrict__ A,
                                                 const float* __restrict__ W,
                                                 float* __restrict__ C, int N, int K) {
    gemm_body(A, W, C, N, K, blockIdx.y << 7, blockIdx.x << 6);
}

// fused QKV: blockIdx.x in [0,24); sel = x>>3 chooses weight/output
__global__ __launch_bounds__(256) void gemm_qkv(const float* __restrict__ A,
                                                const float* __restrict__ wq,
                                                const float* __restrict__ wk,
                                                const float* __restrict__ wv,
                                                float* __restrict__ qb,
                                                float* __restrict__ kb,
                                                float* __restrict__ vb) {
    int sel = blockIdx.x >> 3;
    const float* W = (sel == 0) ? wq : (sel == 1) ? wk : wv;
    float* C = (sel == 0) ? qb : (sel == 1) ? kb : vb;
    gemm_body(A, W, C, HDIM, D_MODEL, blockIdx.y << 7, (blockIdx.x & 7) << 6);
}

// ---------------- flash attention: 2-pass online softmax, 256 threads --------
// smem: Qs/Ks/Vs/Ss [64][68] + penal[512]  => 71,680 bytes => 3 CTAs/SM
#define TS 68
#define ATTN_SMEM ((4 * 64 * TS + 512) * 4)

__global__ __launch_bounds__(256) void attn_kernel(const float* __restrict__ q,
                                                   const float* __restrict__ k,
                                                   const float* __restrict__ v,
                                                   const int* __restrict__ mask,
                                                   float* __restrict__ o) {
    extern __shared__ float sm[];
    float* Qs = sm;                 // [64][TS]
    float* Ks = Qs + 64 * TS;       // [64][TS]
    float* Vs = Ks + 64 * TS;       // [64][TS]
    float* Ss = Vs + 64 * TS;       // [64][TS]
    float* penal = Ss + 64 * TS;    // [512]

    const int tid = threadIdx.x;
    const int warp = tid >> 5;
    const int wm = warp & 3;        // 16-row tile of 64
    const int wn = warp >> 2;       // 32-col strip (two 16-wide MMAs)
    const int qt = blockIdx.x;
    const int b  = blockIdx.y >> 3;
    const int h  = blockIdx.y & 7;
    const float slope = exp2f(-(float)(h + 1));
    const float scale = 0.125f;

    // mask penalty
    #pragma unroll
    for (int j = tid; j < L_SEQ; j += 256)
        penal[j] = mask[b * L_SEQ + j] ? 0.f : -1e9f;

    // tile loader indices: 64 rows x 64 cols over 256 threads -> 16 elems each
    const int lr = tid >> 2, lc = (tid & 3) * 16;
    {
        const float* qp = q + (size_t)(b * L_SEQ + qt * 64 + lr) * HDIM + h * DHEAD + lc;
        #pragma unroll
        for (int i = 0; i < 4; i++)
            *(float4*)&Qs[lr * TS + lc + i * 4] = *(const float4*)(qp + i * 4);
    }

    // stats mapping: 4 threads per row, 16 cols each
    const int r = tid >> 2, p = tid & 3;
    const int ig = qt * 64 + r;
    float m = -3e38f, ssum = 0.f;

    // ---- pass 1: online (max, sum) over all KV tiles ----
    for (int kt = 0; kt < 8; kt++) {
        __syncthreads();
        {
            const float* kp = k + (size_t)(b * L_SEQ + kt * 64 + lr) * HDIM + h * DHEAD + lc;
            #pragma unroll
            for (int i = 0; i < 4; i++)
                *(float4*)&Ks[lr * TS + lc + i * 4] = *(const float4*)(kp + i * 4);
        }
        __syncthreads();
        wmma::fragment<wmma::accumulator, 16, 16, 8, float> sacc[2];
        wmma::fill_fragment(sacc[0], 0.f);
        wmma::fill_fragment(sacc[1], 0.f);
        #pragma unroll
        for (int kk = 0; kk < 8; kk++) {
            wmma::fragment<wmma::matrix_a, 16, 16, 8, wmma::precision::tf32, wmma::row_major> af;
            wmma::load_matrix_sync(af, &Qs[(wm * 16) * TS + kk * 8], TS);
            #pragma unroll
            for (int j = 0; j < 2; j++) {
                wmma::fragment<wmma::matrix_b, 16, 16, 8, wmma::precision::tf32, wmma::col_major> bf;
                wmma::load_matrix_sync(bf, &Ks[(wn * 32 + j * 16) * TS + kk * 8], TS);
                wmma::mma_sync(sacc[j], af, bf, sacc[j]);
            }
        }
        #pragma unroll
        for (int j = 0; j < 2; j++)
            wmma::store_matrix_sync(&Ss[(wm * 16) * TS + wn * 32 + j * 16], sacc[j], TS,
                                    wmma::mem_row_major);
        __syncthreads();

        float vbuf[16];
        float tm = -3e38f;
        #pragma unroll
        for (int jj = 0; jj < 16; jj++) {
            int jl = p * 16 + jj, jg = kt * 64 + jl;
            float s = Ss[r * TS + jl] * scale + penal[jg] - slope * fabsf((float)(ig - jg));
            vbuf[jj] = s;
            tm = fmaxf(tm, s);
        }
        tm = fmaxf(tm, __shfl_xor_sync(0xffffffffu, tm, 1));
        tm = fmaxf(tm, __shfl_xor_sync(0xffffffffu, tm, 2));
        float mnew = fmaxf(m, tm);
        float csum = 0.f;
        #pragma unroll
        for (int jj = 0; jj < 16; jj++) csum += __expf(vbuf[jj] - mnew);
        csum += __shfl_xor_sync(0xffffffffu, csum, 1);
        csum += __shfl_xor_sync(0xffffffffu, csum, 2);
        ssum = ssum * __expf(m - mnew) + csum;
        m = mnew;
    }
    const float inv = 1.f / ssum;

    // ---- pass 2: recompute S, normalize P, accumulate O ----
    wmma::fragment<wmma::accumulator, 16, 16, 8, float> oacc[2];
    wmma::fill_fragment(oacc[0], 0.f);
    wmma::fill_fragment(oacc[1], 0.f);

    for (int kt = 0; kt < 8; kt++) {
        __syncthreads();
        {
            const float* kp = k + (size_t)(b * L_SEQ + kt * 64 + lr) * HDIM + h * DHEAD + lc;
            const float* vp = v + (size_t)(b * L_SEQ + kt * 64 + lr) * HDIM + h * DHEAD + lc;
            #pragma unroll
            for (int i = 0; i < 4; i++) {
                *(float4*)&Ks[lr * TS + lc + i * 4] = *(const float4*)(kp + i * 4);
                *(float4*)&Vs[lr * TS + lc + i * 4] = *(const float4*)(vp + i * 4);
            }
        }
        __syncthreads();
        wmma::fragment<wmma::accumulator, 16, 16, 8, float> sacc[2];
        wmma::fill_fragment(sacc[0], 0.f);
        wmma::fill_fragment(sacc[1], 0.f);
        #pragma unroll
        for (int kk = 0; kk < 8; kk++) {
            wmma::fragment<wmma::matrix_a, 16, 16, 8, wmma::precision::tf32, wmma::row_major> af;
            wmma::load_matrix_sync(af, &Qs[(wm * 16) * TS + kk * 8], TS);
            #pragma unroll
            for (int j = 0; j < 2; j++) {
                wmma::fragment<wmma::matrix_b, 16, 16, 8, wmma::precision::tf32, wmma::col_major> bf;
                wmma::load_matrix_sync(bf, &Ks[(wn * 32 + j * 16) * TS + kk * 8], TS);
                wmma::mma_sync(sacc[j], af, bf, sacc[j]);
            }
        }
        #pragma unroll
        for (int j = 0; j < 2; j++)
            wmma::store_matrix_sync(&Ss[(wm * 16) * TS + wn * 32 + j * 16], sacc[j], TS,
                                    wmma::mem_row_major);
        __syncthreads();

        #pragma unroll
        for (int jj = 0; jj < 16; jj++) {
            int jl = p * 16 + jj, jg = kt * 64 + jl;
            float s = Ss[r * TS + jl] * scale + penal[jg] - slope * fabsf((float)(ig - jg));
            Ss[r * TS + jl] = __expf(s - m) * inv;
        }
        __syncthreads();

        #pragma unroll
        for (int kk = 0; kk < 8; kk++) {
            wmma::fragment<wmma::matrix_a, 16, 16, 8, wmma::precision::tf32, wmma::row_major> af;
            wmma::load_matrix_sync(af, &Ss[(wm * 16) * TS + kk * 8], TS);
            #pragma unroll
            for (int j = 0; j < 2; j++) {
                wmma::fragment<wmma::matrix_b, 16, 16, 8, wmma::precision::tf32, wmma::row_major> bf;
                wmma::load_matrix_sync(bf, &Vs[(kk * 8) * TS + wn * 32 + j * 16], TS);
                wmma::mma_sync(oacc[j], af, bf, oacc[j]);
            }
        }
    }
    #pragma unroll
    for (int j = 0; j < 2; j++)
        wmma::store_matrix_sync(o + (size_t)(b * L_SEQ + qt * 64 + wm * 16) * HDIM
                                  + h * DHEAD + wn * 32 + j * 16,
                                oacc[j], HDIM, wmma::mem_row_major);
}

// ---------------- GEGLU with fused b1 bias -----------------------------------
__global__ void glu_kernel(const float* __restrict__ u,
                           const float* __restrict__ b1,
                           float* __restrict__ ua) {
    int idx = blockIdx.x * blockDim.x + threadIdx.x;
    int m = idx >> 10, i = idx & 1023;
    float val  = u[(size_t)m * 2048 + i] + b1[i];
    float gate = u[(size_t)m * 2048 + 1024 + i] + b1[1024 + i];
    ua[idx] = val * gate * normcdff(gate);
}

// ---------------- final projection to 2 logits -------------------------------
__global__ void out_kernel(const float* __restrict__ hh,
                           const float* __restrict__ Wout,
                           const float* __restrict__ bout,
                           float* __restrict__ out) {
    int row = blockIdx.x;
    int d = threadIdx.x;
    float v = hh[(size_t)row * D_MODEL + d];
    float s0 = v * Wout[d * 2 + 0];
    float s1 = v * Wout[d * 2 + 1];
    #pragma unroll
    for (int o2 = 16; o2 > 0; o2 >>= 1) {
        s0 += __shfl_down_sync(0xffffffffu, s0, o2);
        s1 += __shfl_down_sync(0xffffffffu, s1, o2);
    }
    __shared__ float w0[8], w1[8];
    int w = threadIdx.x >> 5, lane = threadIdx.x & 31;
    if (lane == 0) { w0[w] = s0; w1[w] = s1; }
    __syncthreads();
    if (threadIdx.x == 0) {
        float t0 = 0.f, t1 = 0.f;
        #pragma unroll
        for (int i = 0; i < 8; i++) { t0 += w0[i]; t1 += w1[i]; }
        out[row * 2 + 0] = t0 + bout[0];
        out[row * 2 + 1] = t1 + bout[1];
    }
}

// ---------------- host orchestration -----------------------------------------
extern "C" void kernel_launch(void* const* d_in, const int* in_sizes, int n_in,
                              void* d_out, int out_size) {
    (void)in_sizes; (void)n_in; (void)out_size;
    const int*   seq  = (const int*)d_in[0];
    const int*   mask = (const int*)d_in[1];
    const float* emb  = (const float*)d_in[2];
    const float* png  = (const float*)d_in[3];
    const float* pnb  = (const float*)d_in[4];
    const float* ln1g = (const float*)d_in[5];
    const float* ln1b = (const float*)d_in[6];
    const float* Wq   = (const float*)d_in[7];
    const float* Wk   = (const float*)d_in[8];
    const float* Wv   = (const float*)d_in[9];
    const float* Wo   = (const float*)d_in[10];
    const float* ln2g = (const float*)d_in[11];
    const float* ln2b = (const float*)d_in[12];
    const float* W1   = (const float*)d_in[13];
    const float* b1   = (const float*)d_in[14];
    const float* W2   = (const float*)d_in[15];
    const float* b2   = (const float*)d_in[16];
    const float* fng  = (const float*)d_in[17];
    const float* fnb  = (const float*)d_in[18];
    const float* Wout = (const float*)d_in[19];
    const float* bout = (const float*)d_in[20];

    float *x, *h, *t, *qb, *kb, *vb, *ab, *ub, *uab;
    cudaGetSymbolAddress((void**)&x,   g_x);
    cudaGetSymbolAddress((void**)&h,   g_h);
    cudaGetSymbolAddress((void**)&t,   g_t);
    cudaGetSymbolAddress((void**)&qb,  g_q);
    cudaGetSymbolAddress((void**)&kb,  g_k);
    cudaGetSymbolAddress((void**)&vb,  g_v);
    cudaGetSymbolAddress((void**)&ab,  g_attn);
    cudaGetSymbolAddress((void**)&ub,  g_u);
    cudaGetSymbolAddress((void**)&uab, g_ua);

    cudaFuncSetAttribute(attn_kernel, cudaFuncAttributeMaxDynamicSharedMemorySize, ATTN_SMEM);
    cudaFuncSetAttribute(gemm_tf32, cudaFuncAttributeMaxDynamicSharedMemorySize, GEMM_SMEM);
    cudaFuncSetAttribute(gemm_qkv,  cudaFuncAttributeMaxDynamicSharedMemorySize, GEMM_SMEM);

    embed_ln_kernel<<<M_TOK, 256>>>(seq, emb, png, pnb, x);
    ln_kernel<<<M_TOK, 256>>>(x, ln1g, ln1b, h);

    for (int l = 0; l < DEPTH_N; l++) {
        const float* wq  = Wq  + (size_t)l * D_MODEL * HDIM;
        const float* wk  = Wk  + (size_t)l * D_MODEL * HDIM;
        const float* wv  = Wv  + (size_t)l * D_MODEL * HDIM;
        const float* wo  = Wo  + (size_t)l * HDIM * D_MODEL;
        const float* w1  = W1  + (size_t)l * D_MODEL * 2 * INNER_N;
        const float* bb1 = b1  + (size_t)l * 2 * INNER_N;
        const float* w2  = W2  + (size_t)l * INNER_N * D_MODEL;
        const float* bb2 = b2  + (size_t)l * D_MODEL;

        gemm_qkv<<<dim3(24, 32), 256, GEMM_SMEM>>>(h, wq, wk, wv, qb, kb, vb);

        attn_kernel<<<dim3(L_SEQ / 64, 8 * NHEAD), 256, ATTN_SMEM>>>(qb, kb, vb, mask, ab);

        gemm_tf32<<<dim3(D_MODEL / 64, 32), 256, GEMM_SMEM>>>(ab, wo, t, D_MODEL, HDIM);
        add_ln_kernel<<<M_TOK, 256>>>(x, t, nullptr, ln2g + l * D_MODEL, ln2b + l * D_MODEL, h);

        gemm_tf32<<<dim3(2 * INNER_N / 64, 32), 256, GEMM_SMEM>>>(h, w1, ub, 2 * INNER_N, D_MODEL);
        glu_kernel<<<(M_TOK * INNER_N) / 256, 256>>>(ub, bb1, uab);

        gemm_tf32<<<dim3(D_MODEL / 64, 32), 256, GEMM_SMEM>>>(uab, w2, t, D_MODEL, INNER_N);
        if (l < DEPTH_N - 1)
            add_ln_kernel<<<M_TOK, 256>>>(x, t, bb2, ln1g + (l + 1) * D_MODEL,
                                          ln1b + (l + 1) * D_MODEL, h);
        else
            add_ln_kernel<<<M_TOK, 256>>>(x, t, bb2, fng, fnb, h);
    }

    out_kernel<<<M_TOK, 256>>>(h, Wout, bout, (float*)d_out);
}

// round 8
// speedup vs baseline: 1.2448x; 1.1371x over previous
#include <cuda_runtime.h>
#include <stdint.h>
#include <math.h>
#include <mma.h>

using namespace nvcuda;

#define M_TOK   4096     // B*L
#define D_MODEL 256
#define HDIM    512      // H*DH
#define L_SEQ   512
#define NHEAD   8
#define DHEAD   64
#define DEPTH_N 16
#define INNER_N 1024

// ---------------- scratch (device globals; no allocation allowed) -------------
__device__ float g_x   [M_TOK * D_MODEL];
__device__ float g_h   [M_TOK * D_MODEL];
__device__ float g_t   [M_TOK * D_MODEL];
__device__ float g_q   [M_TOK * HDIM];
__device__ float g_k   [M_TOK * HDIM];
__device__ float g_v   [M_TOK * HDIM];
__device__ float g_attn[M_TOK * HDIM];
__device__ float g_u   [M_TOK * 2 * INNER_N];
__device__ float g_ua  [M_TOK * INNER_N];

// ---------------- cp.async helpers -------------------------------------------
__device__ __forceinline__ void cp16(uint32_t dst, const float* src) {
    asm volatile("cp.async.ca.shared.global [%0], [%1], 16;\n" :: "r"(dst), "l"(src));
}
__device__ __forceinline__ void cp_commit() {
    asm volatile("cp.async.commit_group;\n");
}
__device__ __forceinline__ void cp_wait1() {
    asm volatile("cp.async.wait_group 1;\n");
}
__device__ __forceinline__ void cp_wait0() {
    asm volatile("cp.async.wait_group 0;\n");
}

// ---------------- LayerNorm helper (blockDim.x == 256 == D_MODEL) ------------
__device__ __forceinline__ void ln_write(float v, const float* __restrict__ g,
                                         const float* __restrict__ b,
                                         float* __restrict__ y, int row) {
    int d = threadIdx.x;
    float s = v, s2 = v * v;
    #pragma unroll
    for (int o = 16; o > 0; o >>= 1) {
        s  += __shfl_down_sync(0xffffffffu, s,  o);
        s2 += __shfl_down_sync(0xffffffffu, s2, o);
    }
    __shared__ float ws[8], ws2[8];
    __shared__ float mean_s, inv_s;
    int w = threadIdx.x >> 5, lane = threadIdx.x & 31;
    if (lane == 0) { ws[w] = s; ws2[w] = s2; }
    __syncthreads();
    if (threadIdx.x == 0) {
        float t = 0.f, t2 = 0.f;
        #pragma unroll
        for (int i = 0; i < 8; i++) { t += ws[i]; t2 += ws2[i]; }
        float mu  = t  * (1.f / 256.f);
        float var = t2 * (1.f / 256.f) - mu * mu;
        mean_s = mu;
        inv_s  = rsqrtf(var + 1e-5f);
    }
    __syncthreads();
    y[(size_t)row * D_MODEL + d] = (v - mean_s) * inv_s * g[d] + b[d];
}

__global__ void embed_ln_kernel(const int* __restrict__ seq,
                                const float* __restrict__ emb,
                                const float* __restrict__ g,
                                const float* __restrict__ b,
                                float* __restrict__ y) {
    int row = blockIdx.x;
    float v = emb[(size_t)seq[row] * D_MODEL + threadIdx.x];
    ln_write(v, g, b, y, row);
}

__global__ void ln_kernel(const float* __restrict__ x,
                          const float* __restrict__ g,
                          const float* __restrict__ b,
                          float* __restrict__ y) {
    int row = blockIdx.x;
    float v = x[(size_t)row * D_MODEL + threadIdx.x];
    ln_write(v, g, b, y, row);
}

// x[row] += t[row] (+bias); then y[row] = LN(x[row])
__global__ void add_ln_kernel(float* __restrict__ x,
                              const float* __restrict__ t,
                              const float* __restrict__ bias,
                              const float* __restrict__ g,
                              const float* __restrict__ b,
                              float* __restrict__ y) {
    int row = blockIdx.x;
    int d = threadIdx.x;
    size_t idx = (size_t)row * D_MODEL + d;
    float v = x[idx] + t[idx];
    if (bias) v += bias[d];
    x[idx] = v;
    ln_write(v, g, b, y, row);
}

// ---------------- tf32 WMMA GEMM body: 128x64 tile, BK=32, double-buffered ---
#define AS_STAGE (128 * 36)
#define BS_STAGE (32 * 68)
#define GEMM_SMEM ((2 * AS_STAGE + 2 * BS_STAGE) * 4)

__device__ __forceinline__ void gemm_body(const float* __restrict__ A,
                                          const float* __restrict__ W,
                                          float* __restrict__ C,
                                          int N, int K, int bm, int bn) {
    extern __shared__ float dyn[];
    float* As = dyn;
    float* Bs = dyn + 2 * AS_STAGE;
    const int tid = threadIdx.x;
    const int warp = tid >> 5, wm = warp & 3, wn = warp >> 2;
    const int arow = tid >> 1, acol = (tid & 1) * 16;
    const int brow = tid >> 3, bcol = (tid & 7) * 8;
    uint32_t as_u = (uint32_t)__cvta_generic_to_shared(As);
    uint32_t bs_u = (uint32_t)__cvta_generic_to_shared(Bs);

    wmma::fragment<wmma::accumulator, 16, 16, 8, float> acc[2][2];
    #pragma unroll
    for (int i = 0; i < 2; i++)
        #pragma unroll
        for (int j = 0; j < 2; j++)
            wmma::fill_fragment(acc[i][j], 0.0f);

    const int nk = K >> 5;

    // prologue: stage 0
    {
        const float* ap = A + (size_t)(bm + arow) * K + acol;
        uint32_t ad = as_u + (uint32_t)((arow * 36 + acol) * 4);
        #pragma unroll
        for (int i = 0; i < 4; i++) cp16(ad + i * 16, ap + i * 4);
        const float* bp = W + (size_t)brow * N + bn + bcol;
        uint32_t bd = bs_u + (uint32_t)((brow * 68 + bcol) * 4);
        cp16(bd, bp); cp16(bd + 16, bp + 4);
        cp_commit();
    }

    for (int kt = 0; kt < nk; kt++) {
        int st = kt & 1;
        if (kt + 1 < nk) {
            int k0 = (kt + 1) << 5;
            int s2 = st ^ 1;
            const float* ap = A + (size_t)(bm + arow) * K + k0 + acol;
            uint32_t ad = as_u + (uint32_t)((s2 * AS_STAGE + arow * 36 + acol) * 4);
            #pragma unroll
            for (int i = 0; i < 4; i++) cp16(ad + i * 16, ap + i * 4);
            const float* bp = W + (size_t)(k0 + brow) * N + bn + bcol;
            uint32_t bd = bs_u + (uint32_t)((s2 * BS_STAGE + brow * 68 + bcol) * 4);
            cp16(bd, bp); cp16(bd + 16, bp + 4);
            cp_commit();
            cp_wait1();
        } else {
            cp_wait0();
        }
        __syncthreads();

        const float* Ab = As + st * AS_STAGE;
        const float* Bb = Bs + st * BS_STAGE;
        #pragma unroll
        for (int kk = 0; kk < 4; kk++) {
            wmma::fragment<wmma::matrix_a, 16, 16, 8, wmma::precision::tf32, wmma::row_major> af[2];
            wmma::fragment<wmma::matrix_b, 16, 16, 8, wmma::precision::tf32, wmma::row_major> bf[2];
            #pragma unroll
            for (int i = 0; i < 2; i++) {
                wmma::load_matrix_sync(af[i], Ab + (wm * 32 + i * 16) * 36 + kk * 8, 36);
                #pragma unroll
                for (int e = 0; e < af[i].num_elements; e++)
                    af[i].x[e] = wmma::__float_to_tf32(af[i].x[e]);
            }
            #pragma unroll
            for (int j = 0; j < 2; j++) {
                wmma::load_matrix_sync(bf[j], Bb + (kk * 8) * 68 + wn * 32 + j * 16, 68);
                #pragma unroll
                for (int e = 0; e < bf[j].num_elements; e++)
                    bf[j].x[e] = wmma::__float_to_tf32(bf[j].x[e]);
            }
            #pragma unroll
            for (int i = 0; i < 2; i++)
                #pragma unroll
                for (int j = 0; j < 2; j++)
                    wmma::mma_sync(acc[i][j], af[i], bf[j], acc[i][j]);
        }
        __syncthreads();
    }

    #pragma unroll
    for (int i = 0; i < 2; i++)
        #pragma unroll
        for (int j = 0; j < 2; j++)
            wmma::store_matrix_sync(C + (size_t)(bm + wm * 32 + i * 16) * N + bn + wn * 32 + j * 16,
                                    acc[i][j], N, wmma::mem_row_major);
}

__global__ __launch_bounds__(256) void gemm_tf32(const float* __restrict__ A,
                                                 const float* __restrict__ W,
                                                 float* __restrict__ C, int N, int K) {
    gemm_body(A, W, C, N, K, blockIdx.y << 7, blockIdx.x << 6);
}

// fused QKV: blockIdx.x in [0,24); sel = x>>3 chooses weight/output
__global__ __launch_bounds__(256) void gemm_qkv(const float* __restrict__ A,
                                                const float* __restrict__ wq,
                                                const float* __restrict__ wk,
                                                const float* __restrict__ wv,
                                                float* __restrict__ qb,
                                                float* __restrict__ kb,
                                                float* __restrict__ vb) {
    int sel = blockIdx.x >> 3;
    const float* W = (sel == 0) ? wq : (sel == 1) ? wk : wv;
    float* C = (sel == 0) ? qb : (sel == 1) ? kb : vb;
    gemm_body(A, W, C, HDIM, D_MODEL, blockIdx.y << 7, (blockIdx.x & 7) << 6);
}

// ---------------- single-pass attention with deterministic row shift ---------
// Shift msh_i = max_j(penal[j] - slope*|i-j|) bounds s-msh in [-few, +few]:
// no overflow, and ssum >= exp(qk at the argmax key) > 0 always.
// smem: Qs/Ks/Vs/Ss [64][68] + penal[512] => 71,680 bytes
#define TS 68
#define ATTN_SMEM ((4 * 64 * TS + 512) * 4)

__global__ __launch_bounds__(256) void attn_kernel(const float* __restrict__ q,
                                                   const float* __restrict__ k,
                                                   const float* __restrict__ v,
                                                   const int* __restrict__ mask,
                                                   float* __restrict__ o) {
    extern __shared__ float sm[];
    float* Qs = sm;                 // [64][TS]
    float* Ks = Qs + 64 * TS;       // [64][TS]
    float* Vs = Ks + 64 * TS;       // [64][TS]
    float* Ss = Vs + 64 * TS;       // [64][TS]
    float* penal = Ss + 64 * TS;    // [512]

    const int tid = threadIdx.x;
    const int warp = tid >> 5;
    const int wm = warp & 3;        // 16-row tile of 64
    const int wn = warp >> 2;       // 32-col strip (two 16-wide MMAs)
    const int qt = blockIdx.x;
    const int b  = blockIdx.y >> 3;
    const int h  = blockIdx.y & 7;
    const float slope = exp2f(-(float)(h + 1));
    const float scale = 0.125f;

    for (int j = tid; j < L_SEQ; j += 256)
        penal[j] = mask[b * L_SEQ + j] ? 0.f : -1e9f;

    const int lr = tid >> 2, lc = (tid & 3) * 16;
    {
        const float* qp = q + (size_t)(b * L_SEQ + qt * 64 + lr) * HDIM + h * DHEAD + lc;
        #pragma unroll
        for (int i = 0; i < 4; i++)
            *(float4*)&Qs[lr * TS + lc + i * 4] = *(const float4*)(qp + i * 4);
    }
    __syncthreads();   // penal visible to all threads

    // stats mapping: 4 threads per row, 16 local cols each
    const int r = tid >> 2, p = tid & 3;
    const int ig = qt * 64 + r;

    // per-row shift: max over all keys of (penal - slope*|i-j|)
    float msh = -3e38f;
    for (int jj = 0; jj < 128; jj++) {
        int jg = p * 128 + jj;
        msh = fmaxf(msh, penal[jg] - slope * fabsf((float)(ig - jg)));
    }
    msh = fmaxf(msh, __shfl_xor_sync(0xffffffffu, msh, 1));
    msh = fmaxf(msh, __shfl_xor_sync(0xffffffffu, msh, 2));

    float ssum = 0.f;

    wmma::fragment<wmma::accumulator, 16, 16, 8, float> oacc[2];
    wmma::fill_fragment(oacc[0], 0.f);
    wmma::fill_fragment(oacc[1], 0.f);

    for (int kt = 0; kt < 8; kt++) {
        __syncthreads();
        {
            const float* kp = k + (size_t)(b * L_SEQ + kt * 64 + lr) * HDIM + h * DHEAD + lc;
            const float* vp = v + (size_t)(b * L_SEQ + kt * 64 + lr) * HDIM + h * DHEAD + lc;
            #pragma unroll
            for (int i = 0; i < 4; i++) {
                *(float4*)&Ks[lr * TS + lc + i * 4] = *(const float4*)(kp + i * 4);
                *(float4*)&Vs[lr * TS + lc + i * 4] = *(const float4*)(vp + i * 4);
            }
        }
        __syncthreads();
        {
            wmma::fragment<wmma::accumulator, 16, 16, 8, float> sacc[2];
            wmma::fill_fragment(sacc[0], 0.f);
            wmma::fill_fragment(sacc[1], 0.f);
            #pragma unroll
            for (int kk = 0; kk < 8; kk++) {
                wmma::fragment<wmma::matrix_a, 16, 16, 8, wmma::precision::tf32, wmma::row_major> af;
                wmma::load_matrix_sync(af, &Qs[(wm * 16) * TS + kk * 8], TS);
                #pragma unroll
                for (int j = 0; j < 2; j++) {
                    wmma::fragment<wmma::matrix_b, 16, 16, 8, wmma::precision::tf32, wmma::col_major> bf;
                    wmma::load_matrix_sync(bf, &Ks[(wn * 32 + j * 16) * TS + kk * 8], TS);
                    wmma::mma_sync(sacc[j], af, bf, sacc[j]);
                }
            }
            #pragma unroll
            for (int j = 0; j < 2; j++)
                wmma::store_matrix_sync(&Ss[(wm * 16) * TS + wn * 32 + j * 16], sacc[j], TS,
                                        wmma::mem_row_major);
        }
        __syncthreads();

        // exp(s - msh) in place + row-sum accumulation
        #pragma unroll
        for (int jj = 0; jj < 16; jj++) {
            int jl = p * 16 + jj, jg = kt * 64 + jl;
            float s = Ss[r * TS + jl] * scale + penal[jg] - slope * fabsf((float)(ig - jg));
            float e = __expf(s - msh);
            Ss[r * TS + jl] = e;
            ssum += e;
        }
        __syncthreads();

        #pragma unroll
        for (int kk = 0; kk < 8; kk++) {
            wmma::fragment<wmma::matrix_a, 16, 16, 8, wmma::precision::tf32, wmma::row_major> af;
            wmma::load_matrix_sync(af, &Ss[(wm * 16) * TS + kk * 8], TS);
            #pragma unroll
            for (int j = 0; j < 2; j++) {
                wmma::fragment<wmma::matrix_b, 16, 16, 8, wmma::precision::tf32, wmma::row_major> bf;
                wmma::load_matrix_sync(bf, &Vs[(kk * 8) * TS + wn * 32 + j * 16], TS);
                wmma::mma_sync(oacc[j], af, bf, oacc[j]);
            }
        }
    }

    // combine row sums across the 4 threads of each row
    ssum += __shfl_xor_sync(0xffffffffu, ssum, 1);
    ssum += __shfl_xor_sync(0xffffffffu, ssum, 2);
    const float inv = 1.f / ssum;

    // stage O fragments through smem, then scaled write-out
    __syncthreads();   // all PV MMA reads of Ss complete before overwrite
    #pragma unroll
    for (int j = 0; j < 2; j++)
        wmma::store_matrix_sync(&Ss[(wm * 16) * TS + wn * 32 + j * 16], oacc[j], TS,
                                wmma::mem_row_major);
    __syncthreads();

    {
        float* op = o + (size_t)(b * L_SEQ + qt * 64 + r) * HDIM + h * DHEAD + p * 16;
        #pragma unroll
        for (int i = 0; i < 4; i++) {
            float4 vv = *(float4*)&Ss[r * TS + p * 16 + i * 4];
            vv.x *= inv; vv.y *= inv; vv.z *= inv; vv.w *= inv;
            *(float4*)(op + i * 4) = vv;
        }
    }
}

// ---------------- GEGLU with fused b1 bias -----------------------------------
__global__ void glu_kernel(const float* __restrict__ u,
                           const float* __restrict__ b1,
                           float* __restrict__ ua) {
    int idx = blockIdx.x * blockDim.x + threadIdx.x;
    int m = idx >> 10, i = idx & 1023;
    float val  = u[(size_t)m * 2048 + i] + b1[i];
    float gate = u[(size_t)m * 2048 + 1024 + i] + b1[1024 + i];
    ua[idx] = val * gate * normcdff(gate);
}

// ---------------- final projection to 2 logits -------------------------------
__global__ void out_kernel(const float* __restrict__ hh,
                           const float* __restrict__ Wout,
                           const float* __restrict__ bout,
                           float* __restrict__ out) {
    int row = blockIdx.x;
    int d = threadIdx.x;
    float v = hh[(size_t)row * D_MODEL + d];
    float s0 = v * Wout[d * 2 + 0];
    float s1 = v * Wout[d * 2 + 1];
    #pragma unroll
    for (int o2 = 16; o2 > 0; o2 >>= 1) {
        s0 += __shfl_down_sync(0xffffffffu, s0, o2);
        s1 += __shfl_down_sync(0xffffffffu, s1, o2);
    }
    __shared__ float w0[8], w1[8];
    int w = threadIdx.x >> 5, lane = threadIdx.x & 31;
    if (lane == 0) { w0[w] = s0; w1[w] = s1; }
    __syncthreads();
    if (threadIdx.x == 0) {
        float t0 = 0.f, t1 = 0.f;
        #pragma unroll
        for (int i = 0; i < 8; i++) { t0 += w0[i]; t1 += w1[i]; }
        out[row * 2 + 0] = t0 + bout[0];
        out[row * 2 + 1] = t1 + bout[1];
    }
}

// ---------------- host orchestration -----------------------------------------
extern "C" void kernel_launch(void* const* d_in, const int* in_sizes, int n_in,
                              void* d_out, int out_size) {
    (void)in_sizes; (void)n_in; (void)out_size;
    const int*   seq  = (const int*)d_in[0];
    const int*   mask = (const int*)d_in[1];
    const float* emb  = (const float*)d_in[2];
    const float* png  = (const float*)d_in[3];
    const float* pnb  = (const float*)d_in[4];
    const float* ln1g = (const float*)d_in[5];
    const float* ln1b = (const float*)d_in[6];
    const float* Wq   = (const float*)d_in[7];
    const float* Wk   = (const float*)d_in[8];
    const float* Wv   = (const float*)d_in[9];
    const float* Wo   = (const float*)d_in[10];
    const float* ln2g = (const float*)d_in[11];
    const float* ln2b = (const float*)d_in[12];
    const float* W1   = (const float*)d_in[13];
    const float* b1   = (const float*)d_in[14];
    const float* W2   = (const float*)d_in[15];
    const float* b2   = (const float*)d_in[16];
    const float* fng  = (const float*)d_in[17];
    const float* fnb  = (const float*)d_in[18];
    const float* Wout = (const float*)d_in[19];
    const float* bout = (const float*)d_in[20];

    float *x, *h, *t, *qb, *kb, *vb, *ab, *ub, *uab;
    cudaGetSymbolAddress((void**)&x,   g_x);
    cudaGetSymbolAddress((void**)&h,   g_h);
    cudaGetSymbolAddress((void**)&t,   g_t);
    cudaGetSymbolAddress((void**)&qb,  g_q);
    cudaGetSymbolAddress((void**)&kb,  g_k);
    cudaGetSymbolAddress((void**)&vb,  g_v);
    cudaGetSymbolAddress((void**)&ab,  g_attn);
    cudaGetSymbolAddress((void**)&ub,  g_u);
    cudaGetSymbolAddress((void**)&uab, g_ua);

    cudaFuncSetAttribute(attn_kernel, cudaFuncAttributeMaxDynamicSharedMemorySize, ATTN_SMEM);
    cudaFuncSetAttribute(gemm_tf32, cudaFuncAttributeMaxDynamicSharedMemorySize, GEMM_SMEM);
    cudaFuncSetAttribute(gemm_qkv,  cudaFuncAttributeMaxDynamicSharedMemorySize, GEMM_SMEM);

    embed_ln_kernel<<<M_TOK, 256>>>(seq, emb, png, pnb, x);
    ln_kernel<<<M_TOK, 256>>>(x, ln1g, ln1b, h);

    for (int l = 0; l < DEPTH_N; l++) {
        const float* wq  = Wq  + (size_t)l * D_MODEL * HDIM;
        const float* wk  = Wk  + (size_t)l * D_MODEL * HDIM;
        const float* wv  = Wv  + (size_t)l * D_MODEL * HDIM;
        const float* wo  = Wo  + (size_t)l * HDIM * D_MODEL;
        const float* w1  = W1  + (size_t)l * D_MODEL * 2 * INNER_N;
        const float* bb1 = b1  + (size_t)l * 2 * INNER_N;
        const float* w2  = W2  + (size_t)l * INNER_N * D_MODEL;
        const float* bb2 = b2  + (size_t)l * D_MODEL;

        gemm_qkv<<<dim3(24, 32), 256, GEMM_SMEM>>>(h, wq, wk, wv, qb, kb, vb);

        attn_kernel<<<dim3(L_SEQ / 64, 8 * NHEAD), 256, ATTN_SMEM>>>(qb, kb, vb, mask, ab);

        gemm_tf32<<<dim3(D_MODEL / 64, 32), 256, GEMM_SMEM>>>(ab, wo, t, D_MODEL, HDIM);
        add_ln_kernel<<<M_TOK, 256>>>(x, t, nullptr, ln2g + l * D_MODEL, ln2b + l * D_MODEL, h);

        gemm_tf32<<<dim3(2 * INNER_N / 64, 32), 256, GEMM_SMEM>>>(h, w1, ub, 2 * INNER_N, D_MODEL);
        glu_kernel<<<(M_TOK * INNER_N) / 256, 256>>>(ub, bb1, uab);

        gemm_tf32<<<dim3(D_MODEL / 64, 32), 256, GEMM_SMEM>>>(uab, w2, t, D_MODEL, INNER_N);
        if (l < DEPTH_N - 1)
            add_ln_kernel<<<M_TOK, 256>>>(x, t, bb2, ln1g + (l + 1) * D_MODEL,
                                          ln1b + (l + 1) * D_MODEL, h);
        else
            add_ln_kernel<<<M_TOK, 256>>>(x, t, bb2, fng, fnb, h);
    }

    out_kernel<<<M_TOK, 256>>>(h, Wout, bout, (float*)d_out);
}